// round 5
// baseline (speedup 1.0000x reference)
#include <cuda_runtime.h>

// ALIF forward scan, float2-vectorized + software-pipelined.
// x_seq: [T, n_flat] fp32; state v, a: [n_flat]; out spikes [T, n_flat] fp32.
// Per step: v = dv*v + x; th = th0 + beta*a; s = (v>th); v -= s*th; a = da*a + s.
//
// Each thread owns 2 adjacent neurons (float2 lanes): 2 independent recurrence
// chains (ILP) and LDG.64/STG.64 (half the memory instructions). Double-buffered
// prefetch of 16 timesteps keeps 4KB/warp of loads in flight during compute.

#define U 16

__device__ __forceinline__ float alif_step(float& v, float& a, float xv,
                                           float dv, float da, float th0, float beta) {
    v = fmaf(dv, v, xv);
    float th = fmaf(beta, a, th0);
    float s = (v > th) ? 1.0f : 0.0f;
    v = fmaf(-s, th, v);
    a = fmaf(da, a, s);
    return s;
}

__global__ __launch_bounds__(32)
void ALIF_24309514895931_kernel(const float2* __restrict__ x,
                                const float2* __restrict__ v0,
                                const float2* __restrict__ a0,
                                const float* __restrict__ dv_p,
                                const float* __restrict__ da_p,
                                const float* __restrict__ th_p,
                                const float* __restrict__ beta_p,
                                float2* __restrict__ out,
                                int n2, int T) {
    int i = blockIdx.x * 32 + threadIdx.x;
    if (i >= n2) return;

    const float dv   = *dv_p;
    const float da   = *da_p;
    const float th0  = *th_p;
    const float beta = *beta_p;

    float2 v = v0[i];
    float2 a = a0[i];

    const float2* xp = x + i;
    float2* op = out + i;
    const unsigned stride = (unsigned)n2;

    const int nb = T / U;

    float2 bufA[U], bufB[U];

#define LOADBLK(buf, b)                                                     \
    {                                                                       \
        unsigned base = (unsigned)(b) * U * stride;                         \
        _Pragma("unroll")                                                   \
        for (int k = 0; k < U; k++)                                         \
            (buf)[k] = __ldcs(xp + base + (unsigned)k * stride);            \
    }

#define COMPBLK(buf, b)                                                     \
    {                                                                       \
        unsigned base = (unsigned)(b) * U * stride;                         \
        _Pragma("unroll")                                                   \
        for (int k = 0; k < U; k++) {                                       \
            float2 s;                                                       \
            s.x = alif_step(v.x, a.x, (buf)[k].x, dv, da, th0, beta);       \
            s.y = alif_step(v.y, a.y, (buf)[k].y, dv, da, th0, beta);       \
            __stcs(op + base + (unsigned)k * stride, s);                    \
        }                                                                   \
    }

    if (nb > 0) LOADBLK(bufA, 0);

    int b = 0;
    for (; b + 2 <= nb; b += 2) {
        LOADBLK(bufB, b + 1);          // prefetch next block
        COMPBLK(bufA, b);              // compute current while loads in flight
        if (b + 2 < nb) LOADBLK(bufA, b + 2);
        COMPBLK(bufB, b + 1);
    }
    if (b < nb) {                      // odd nb: last block already resident
        COMPBLK(bufA, b);
    }

    // tail (T not a multiple of U)
    for (int t = nb * U; t < T; t++) {
        float2 xv = __ldcs(xp + (unsigned)t * stride);
        float2 s;
        s.x = alif_step(v.x, a.x, xv.x, dv, da, th0, beta);
        s.y = alif_step(v.y, a.y, xv.y, dv, da, th0, beta);
        __stcs(op + (unsigned)t * stride, s);
    }
#undef LOADBLK
#undef COMPBLK
}

extern "C" void kernel_launch(void* const* d_in, const int* in_sizes, int n_in,
                              void* d_out, int out_size) {
    // metadata order: x_seq, v, a, decay_v, decay_a, threshold, beta, alpha
    const float* x      = (const float*)d_in[0];
    const float* v0     = (const float*)d_in[1];
    const float* a0     = (const float*)d_in[2];
    const float* dv_p   = (const float*)d_in[3];
    const float* da_p   = (const float*)d_in[4];
    const float* th_p   = (const float*)d_in[5];
    const float* beta_p = (const float*)d_in[6];
    // alpha (d_in[7]) only affects backward surrogate; unused in forward.

    int n_flat = in_sizes[1];
    int T      = in_sizes[0] / n_flat;

    int n2 = n_flat / 2;                 // float2 elements per timestep
    float* out = (float*)d_out;

    int threads = 32;
    int blocks = (n2 + threads - 1) / threads;   // 1024 for n_flat=65536
    ALIF_24309514895931_kernel<<<blocks, threads>>>(
        (const float2*)x, (const float2*)v0, (const float2*)a0,
        dv_p, da_p, th_p, beta_p, (float2*)out, n2, T);
}

// round 6
// speedup vs baseline: 1.1450x; 1.1450x over previous
#include <cuda_runtime.h>

// ALIF forward scan, scalar thread-per-neuron with depth-32 rolling ring prefetch.
// x_seq: [T, n_flat] fp32; state v, a: [n_flat]; out spikes [T, n_flat] fp32.
// Per step: v = dv*v + x; th = th0 + beta*a; s = (v>th); v -= s*th; a = da*a + s.
//
// Instead of burst load-16 / compute-16 (sawtooth queue occupancy, cross-CTA
// L1tex contention from front-batched LDGs), each step consumes ring slot k and
// immediately issues the load for step t+D into the same slot: a steady ~D
// loads per thread stay in flight for the whole kernel. D=32 trails consumption
// by > DRAM latency, fully hiding memory.

#define D 32

__device__ __forceinline__ float alif_step(float& v, float& a, float xv,
                                           float dv, float da, float th0, float beta) {
    v = fmaf(dv, v, xv);
    float th = fmaf(beta, a, th0);
    float s = (v > th) ? 1.0f : 0.0f;
    v = fmaf(-s, th, v);
    a = fmaf(da, a, s);
    return s;
}

__global__ __launch_bounds__(64)
void ALIF_24309514895931_kernel(const float* __restrict__ x,
                                const float* __restrict__ v0,
                                const float* __restrict__ a0,
                                const float* __restrict__ dv_p,
                                const float* __restrict__ da_p,
                                const float* __restrict__ th_p,
                                const float* __restrict__ beta_p,
                                float* __restrict__ out,
                                int n_flat, int T) {
    int i = blockIdx.x * 64 + threadIdx.x;
    if (i >= n_flat) return;

    const float dv   = *dv_p;
    const float da   = *da_p;
    const float th0  = *th_p;
    const float beta = *beta_p;

    float v = v0[i];
    float a = a0[i];

    const float* xp = x + i;
    float* op = out + i;
    const unsigned stride = (unsigned)n_flat;

    const int nb = T / D;   // full ring blocks

    float buf[D];

    if (nb > 0) {
        // Prologue: fill the ring with steps 0..D-1.
        #pragma unroll
        for (int k = 0; k < D; k++)
            buf[k] = __ldcs(xp + (unsigned)k * stride);

        // Main: for each block b, consume step t=b*D+k and prefetch t+D.
        for (int b = 0; b < nb - 1; b++) {
            unsigned base  = (unsigned)b * D * stride;
            unsigned pbase = base + (unsigned)D * stride;
            #pragma unroll
            for (int k = 0; k < D; k++) {
                float xv = buf[k];
                buf[k] = __ldcs(xp + pbase + (unsigned)k * stride);  // steady prefetch
                float s = alif_step(v, a, xv, dv, da, th0, beta);
                __stcs(op + base + (unsigned)k * stride, s);
            }
        }

        // Epilogue: consume the last resident block (no prefetch).
        {
            unsigned base = (unsigned)(nb - 1) * D * stride;
            #pragma unroll
            for (int k = 0; k < D; k++) {
                float s = alif_step(v, a, buf[k], dv, da, th0, beta);
                __stcs(op + base + (unsigned)k * stride, s);
            }
        }
    }

    // Tail (T not a multiple of D).
    for (int t = nb * D; t < T; t++) {
        float xv = __ldcs(xp + (unsigned)t * stride);
        float s = alif_step(v, a, xv, dv, da, th0, beta);
        __stcs(op + (unsigned)t * stride, s);
    }
}

extern "C" void kernel_launch(void* const* d_in, const int* in_sizes, int n_in,
                              void* d_out, int out_size) {
    // metadata order: x_seq, v, a, decay_v, decay_a, threshold, beta, alpha
    const float* x      = (const float*)d_in[0];
    const float* v0     = (const float*)d_in[1];
    const float* a0     = (const float*)d_in[2];
    const float* dv_p   = (const float*)d_in[3];
    const float* da_p   = (const float*)d_in[4];
    const float* th_p   = (const float*)d_in[5];
    const float* beta_p = (const float*)d_in[6];
    // alpha (d_in[7]) only affects backward surrogate; unused in forward.

    int n_flat = in_sizes[1];
    int T      = in_sizes[0] / n_flat;

    float* out = (float*)d_out;

    int threads = 64;
    int blocks = (n_flat + threads - 1) / threads;   // 1024 for n_flat=65536
    ALIF_24309514895931_kernel<<<blocks, threads>>>(
        x, v0, a0, dv_p, da_p, th_p, beta_p, out, n_flat, T);
}